// round 4
// baseline (speedup 1.0000x reference)
#include <cuda_runtime.h>
#include <cuda_fp16.h>
#include <cstdint>
#include <math.h>

#define B_ 4
#define L_ 4096
#define H_ 16
#define DH_ 128
#define DV_ 128
#define CHUNK_ 1024
#define NCHUNK_ 4
#define QT_ 64
#define KT_ 64
#define PADH 136
#define PADV 136
#define THREADS_ 128
#define SCALE_ 0.08838834764831845f  /* 1/sqrt(128) */

// Q hi/lo + K hi/lo + V hi/lo
#define SMEM_BYTES ((4 * QT_ * PADH + 2 * KT_ * PADV) * 2)

// RoPE cos/sin table: [L_][64] of (cos, sin)
__device__ float2 g_rope[L_ * 64];

__global__ void rope_table_kernel() {
    int idx = blockIdx.x * blockDim.x + threadIdx.x;
    if (idx >= L_ * 64) return;
    int pos = idx >> 6;
    int j = idx & 63;
    const float coef = -0.14391156831212787f;  // -ln(10000)/64  (FIXED)
    float freq = expf((float)j * coef);
    float ang = (float)pos * freq;   // fp32 rounding matches reference
    float s, c;
    sincosf(ang, &s, &c);
    g_rope[idx] = make_float2(c, s);
}

__device__ __forceinline__ void ldm_x4(uint32_t r[4], const half* p) {
    uint32_t a = (uint32_t)__cvta_generic_to_shared(p);
    asm volatile("ldmatrix.sync.aligned.m8n8.x4.shared.b16 {%0,%1,%2,%3}, [%4];\n"
                 : "=r"(r[0]), "=r"(r[1]), "=r"(r[2]), "=r"(r[3]) : "r"(a));
}
__device__ __forceinline__ void ldm_x4_t(uint32_t r[4], const half* p) {
    uint32_t a = (uint32_t)__cvta_generic_to_shared(p);
    asm volatile("ldmatrix.sync.aligned.m8n8.x4.trans.shared.b16 {%0,%1,%2,%3}, [%4];\n"
                 : "=r"(r[0]), "=r"(r[1]), "=r"(r[2]), "=r"(r[3]) : "r"(a));
}
__device__ __forceinline__ void mma16816(float c[4], const uint32_t a[4],
                                         uint32_t b0, uint32_t b1) {
    asm volatile(
        "mma.sync.aligned.m16n8k16.row.col.f32.f16.f16.f32 "
        "{%0,%1,%2,%3}, {%4,%5,%6,%7}, {%8,%9}, {%0,%1,%2,%3};\n"
        : "+f"(c[0]), "+f"(c[1]), "+f"(c[2]), "+f"(c[3])
        : "r"(a[0]), "r"(a[1]), "r"(a[2]), "r"(a[3]), "r"(b0), "r"(b1));
}

__global__ __launch_bounds__(THREADS_, 1) void attn_kernel(
    const float* __restrict__ q, const float* __restrict__ k,
    const float* __restrict__ v, float* __restrict__ out) {
    extern __shared__ half smem[];
    half* sQh = smem;                  // [QT_][PADH] fp16 hi
    half* sQl = sQh + QT_ * PADH;      // fp16 lo residual
    half* sKh = sQl + QT_ * PADH;
    half* sKl = sKh + KT_ * PADH;
    half* sVh = sKl + KT_ * PADH;      // [KT_][PADV]
    half* sVl = sVh + KT_ * PADV;

    int bid = blockIdx.x;
    int qt = bid & 15;
    int h  = (bid >> 4) & 15;
    int n  = (bid >> 8) & 3;
    int b  = bid >> 10;

    int tid  = threadIdx.x;
    int warp = tid >> 5;
    int lane = tid & 31;
    int q0 = qt * QT_;

    // ---- load Q tile: RoPE + fp16 hi/lo split ----
    {
        int p  = tid & 63;
        int r0 = tid >> 6;
        for (int r = r0; r < QT_; r += 2) {
            int gl = n * CHUNK_ + q0 + r;
            const float* row = q + ((size_t)((b * L_ + gl) * H_ + h)) * DH_;
            float x1 = row[p], x2 = row[p + 64];
            float2 cs = g_rope[gl * 64 + p];
            float y1 = x1 * cs.x - x2 * cs.y;
            float y2 = x2 * cs.x + x1 * cs.y;
            half h1 = __float2half_rn(y1);
            half h2 = __float2half_rn(y2);
            sQh[r * PADH + p]      = h1;
            sQh[r * PADH + p + 64] = h2;
            sQl[r * PADH + p]      = __float2half_rn(y1 - __half2float(h1));
            sQl[r * PADH + p + 64] = __float2half_rn(y2 - __half2float(h2));
        }
    }

    float acc[16][4];
#pragma unroll
    for (int i = 0; i < 16; i++)
#pragma unroll
        for (int j2 = 0; j2 < 4; j2++) acc[i][j2] = 0.f;
    float m0 = -1e30f, m1 = -1e30f, l0 = 0.f, l1 = 0.f;

    for (int kt = 0; kt <= qt; kt++) {
        __syncthreads();
        // ---- load K tile: RoPE + split ----
        {
            int p  = tid & 63;
            int r0 = tid >> 6;
            for (int r = r0; r < KT_; r += 2) {
                int gl = n * CHUNK_ + kt * KT_ + r;
                const float* row = k + ((size_t)((b * L_ + gl) * H_ + h)) * DH_;
                float x1 = row[p], x2 = row[p + 64];
                float2 cs = g_rope[gl * 64 + p];
                float y1 = x1 * cs.x - x2 * cs.y;
                float y2 = x2 * cs.x + x1 * cs.y;
                half h1 = __float2half_rn(y1);
                half h2 = __float2half_rn(y2);
                sKh[r * PADH + p]      = h1;
                sKh[r * PADH + p + 64] = h2;
                sKl[r * PADH + p]      = __float2half_rn(y1 - __half2float(h1));
                sKl[r * PADH + p + 64] = __float2half_rn(y2 - __half2float(h2));
            }
        }
        // ---- load V tile (fp16 hi/lo split) ----
        {
            int c4 = tid & 31;
            int r0 = tid >> 5;
            for (int r = r0; r < KT_; r += 4) {
                int gl = n * CHUNK_ + kt * KT_ + r;
                const float4* row =
                    (const float4*)(v + ((size_t)((b * L_ + gl) * H_ + h)) * DV_);
                float4 f = row[c4];
                half hx = __float2half_rn(f.x);
                half hy = __float2half_rn(f.y);
                half hz = __float2half_rn(f.z);
                half hw = __float2half_rn(f.w);
                half2 a01, a23, b01, b23;
                a01 = __halves2half2(hx, hy);
                a23 = __halves2half2(hz, hw);
                b01 = __floats2half2_rn(f.x - __half2float(hx), f.y - __half2float(hy));
                b23 = __floats2half2_rn(f.z - __half2float(hz), f.w - __half2float(hw));
                *(half2*)&sVh[r * PADV + c4 * 4]     = a01;
                *(half2*)&sVh[r * PADV + c4 * 4 + 2] = a23;
                *(half2*)&sVl[r * PADV + c4 * 4]     = b01;
                *(half2*)&sVl[r * PADV + c4 * 4 + 2] = b23;
            }
        }
        __syncthreads();

        // ---- S = Q K^T (split: Qh*Kh + Qh*Kl + Ql*Kh) ----
        float sacc[8][4];
#pragma unroll
        for (int j = 0; j < 8; j++)
#pragma unroll
            for (int j2 = 0; j2 < 4; j2++) sacc[j][j2] = 0.f;

#pragma unroll
        for (int ks = 0; ks < 8; ks++) {
            uint32_t aH[4], aL[4];
            int aoff = (warp * 16 + (lane & 15)) * PADH + ks * 16 + ((lane >> 4) << 3);
            ldm_x4(aH, sQh + aoff);
            ldm_x4(aL, sQl + aoff);
#pragma unroll
            for (int jp = 0; jp < 4; jp++) {
                int g = lane >> 3;
                int boff = (jp * 16 + ((g >> 1) << 3) + (lane & 7)) * PADH +
                           ks * 16 + ((g & 1) << 3);
                uint32_t bH[4], bL[4];
                ldm_x4(bH, sKh + boff);
                ldm_x4(bL, sKl + boff);
                mma16816(sacc[2 * jp],     aH, bH[0], bH[1]);
                mma16816(sacc[2 * jp + 1], aH, bH[2], bH[3]);
                mma16816(sacc[2 * jp],     aH, bL[0], bL[1]);
                mma16816(sacc[2 * jp + 1], aH, bL[2], bL[3]);
                mma16816(sacc[2 * jp],     aL, bH[0], bH[1]);
                mma16816(sacc[2 * jp + 1], aL, bH[2], bH[3]);
            }
        }

        // ---- causal mask on diagonal tile ----
        if (kt == qt) {
            int r_lo = q0 + warp * 16 + (lane >> 2);
#pragma unroll
            for (int j = 0; j < 8; j++) {
                int c = qt * KT_ + j * 8 + ((lane & 3) << 1);
                if (c     > r_lo)     sacc[j][0] = -1e30f;
                if (c + 1 > r_lo)     sacc[j][1] = -1e30f;
                if (c     > r_lo + 8) sacc[j][2] = -1e30f;
                if (c + 1 > r_lo + 8) sacc[j][3] = -1e30f;
            }
        }

        // ---- online softmax (scale folded into exp) ----
        float mx0 = -1e30f, mx1 = -1e30f;
#pragma unroll
        for (int j = 0; j < 8; j++) {
            mx0 = fmaxf(mx0, fmaxf(sacc[j][0], sacc[j][1]));
            mx1 = fmaxf(mx1, fmaxf(sacc[j][2], sacc[j][3]));
        }
        mx0 = fmaxf(mx0, __shfl_xor_sync(0xffffffffu, mx0, 1));
        mx0 = fmaxf(mx0, __shfl_xor_sync(0xffffffffu, mx0, 2));
        mx1 = fmaxf(mx1, __shfl_xor_sync(0xffffffffu, mx1, 1));
        mx1 = fmaxf(mx1, __shfl_xor_sync(0xffffffffu, mx1, 2));
        float mn0 = fmaxf(m0, mx0), mn1 = fmaxf(m1, mx1);
        float al0 = __expf((m0 - mn0) * SCALE_);
        float al1 = __expf((m1 - mn1) * SCALE_);

        float rs0 = 0.f, rs1 = 0.f;
        uint32_t pH[8][2], pL[8][2];
#pragma unroll
        for (int j = 0; j < 8; j++) {
            float p0 = __expf((sacc[j][0] - mn0) * SCALE_);
            float p1 = __expf((sacc[j][1] - mn0) * SCALE_);
            float p2 = __expf((sacc[j][2] - mn1) * SCALE_);
            float p3 = __expf((sacc[j][3] - mn1) * SCALE_);
            rs0 += p0 + p1;
            rs1 += p2 + p3;
            half q0h = __float2half_rn(p0);
            half q1h = __float2half_rn(p1);
            half q2h = __float2half_rn(p2);
            half q3h = __float2half_rn(p3);
            half2 t0 = __halves2half2(q0h, q1h);
            half2 t1 = __halves2half2(q2h, q3h);
            half2 u0 = __floats2half2_rn(p0 - __half2float(q0h), p1 - __half2float(q1h));
            half2 u1 = __floats2half2_rn(p2 - __half2float(q2h), p3 - __half2float(q3h));
            pH[j][0] = *(uint32_t*)&t0;
            pH[j][1] = *(uint32_t*)&t1;
            pL[j][0] = *(uint32_t*)&u0;
            pL[j][1] = *(uint32_t*)&u1;
        }
        rs0 += __shfl_xor_sync(0xffffffffu, rs0, 1);
        rs0 += __shfl_xor_sync(0xffffffffu, rs0, 2);
        rs1 += __shfl_xor_sync(0xffffffffu, rs1, 1);
        rs1 += __shfl_xor_sync(0xffffffffu, rs1, 2);
        l0 = l0 * al0 + rs0;
        l1 = l1 * al1 + rs1;
        m0 = mn0;
        m1 = mn1;
#pragma unroll
        for (int nt = 0; nt < 16; nt++) {
            acc[nt][0] *= al0;
            acc[nt][1] *= al0;
            acc[nt][2] *= al1;
            acc[nt][3] *= al1;
        }

        // ---- O += P V (split: Ph*Vh + Ph*Vl + Pl*Vh) ----
#pragma unroll
        for (int kk = 0; kk < 4; kk++) {
            uint32_t aH[4] = {pH[2 * kk][0], pH[2 * kk][1],
                              pH[2 * kk + 1][0], pH[2 * kk + 1][1]};
            uint32_t aL[4] = {pL[2 * kk][0], pL[2 * kk][1],
                              pL[2 * kk + 1][0], pL[2 * kk + 1][1]};
#pragma unroll
            for (int nb = 0; nb < 8; nb++) {
                int g = lane >> 3;
                int voff = (kk * 16 + ((g & 1) << 3) + (lane & 7)) * PADV +
                           nb * 16 + ((g >> 1) << 3);
                uint32_t bh[4], bl[4];
                ldm_x4_t(bh, sVh + voff);
                ldm_x4_t(bl, sVl + voff);
                mma16816(acc[2 * nb],     aH, bh[0], bh[1]);
                mma16816(acc[2 * nb + 1], aH, bh[2], bh[3]);
                mma16816(acc[2 * nb],     aH, bl[0], bl[1]);
                mma16816(acc[2 * nb + 1], aH, bl[2], bl[3]);
                mma16816(acc[2 * nb],     aL, bh[0], bh[1]);
                mma16816(acc[2 * nb + 1], aL, bh[2], bh[3]);
            }
        }
    }

    // ---- normalize and write out ----
    float il0 = 1.f / l0, il1 = 1.f / l1;
    int gl0 = n * CHUNK_ + q0 + warp * 16 + (lane >> 2);
    float* o0 = out + ((size_t)((b * L_ + gl0) * H_ + h)) * DV_;
    float* o1 = out + ((size_t)((b * L_ + gl0 + 8) * H_ + h)) * DV_;
#pragma unroll
    for (int nt = 0; nt < 16; nt++) {
        int c = nt * 8 + ((lane & 3) << 1);
        float2 w0 = make_float2(acc[nt][0] * il0, acc[nt][1] * il0);
        float2 w1 = make_float2(acc[nt][2] * il1, acc[nt][3] * il1);
        *(float2*)(o0 + c) = w0;
        *(float2*)(o1 + c) = w1;
    }
}

extern "C" void kernel_launch(void* const* d_in, const int* in_sizes, int n_in,
                              void* d_out, int out_size) {
    (void)in_sizes; (void)n_in; (void)out_size;
    const float* q = (const float*)d_in[0];
    const float* k = (const float*)d_in[1];
    const float* v = (const float*)d_in[2];
    float* out = (float*)d_out;

    cudaFuncSetAttribute(attn_kernel, cudaFuncAttributeMaxDynamicSharedMemorySize,
                         SMEM_BYTES);
    rope_table_kernel<<<(L_ * 64 + 255) / 256, 256>>>();
    attn_kernel<<<B_ * NCHUNK_ * H_ * 16, THREADS_, SMEM_BYTES>>>(q, k, v, out);
}

// round 5
// speedup vs baseline: 1.1304x; 1.1304x over previous
#include <cuda_runtime.h>
#include <cuda_fp16.h>
#include <cstdint>
#include <math.h>

#define B_ 4
#define L_ 4096
#define H_ 16
#define DH_ 128
#define DV_ 128
#define CHUNK_ 1024
#define NCHUNK_ 4
#define QT_ 64
#define KT_ 64
#define PADH 136
#define PADV 136
#define THREADS_ 128
#define SCALE_ 0.08838834764831845f  /* 1/sqrt(128) */

// Qh + Kh + Kl + Vh
#define SMEM_BYTES ((QT_ * PADH + 2 * KT_ * PADH + KT_ * PADV) * 2)

// RoPE cos/sin table: [L_][64] of (cos, sin)
__device__ float2 g_rope[L_ * 64];

__global__ void rope_table_kernel() {
    int idx = blockIdx.x * blockDim.x + threadIdx.x;
    if (idx >= L_ * 64) return;
    int pos = idx >> 6;
    int j = idx & 63;
    const float coef = -0.14391156831212787f;  // -ln(10000)/64
    float freq = expf((float)j * coef);
    float ang = (float)pos * freq;   // fp32 rounding matches reference
    float s, c;
    sincosf(ang, &s, &c);
    g_rope[idx] = make_float2(c, s);
}

__device__ __forceinline__ void ldm_x4(uint32_t r[4], const half* p) {
    uint32_t a = (uint32_t)__cvta_generic_to_shared(p);
    asm volatile("ldmatrix.sync.aligned.m8n8.x4.shared.b16 {%0,%1,%2,%3}, [%4];\n"
                 : "=r"(r[0]), "=r"(r[1]), "=r"(r[2]), "=r"(r[3]) : "r"(a));
}
__device__ __forceinline__ void ldm_x4_t(uint32_t r[4], const half* p) {
    uint32_t a = (uint32_t)__cvta_generic_to_shared(p);
    asm volatile("ldmatrix.sync.aligned.m8n8.x4.trans.shared.b16 {%0,%1,%2,%3}, [%4];\n"
                 : "=r"(r[0]), "=r"(r[1]), "=r"(r[2]), "=r"(r[3]) : "r"(a));
}
__device__ __forceinline__ void mma16816(float c[4], const uint32_t a[4],
                                         uint32_t b0, uint32_t b1) {
    asm volatile(
        "mma.sync.aligned.m16n8k16.row.col.f32.f16.f16.f32 "
        "{%0,%1,%2,%3}, {%4,%5,%6,%7}, {%8,%9}, {%0,%1,%2,%3};\n"
        : "+f"(c[0]), "+f"(c[1]), "+f"(c[2]), "+f"(c[3])
        : "r"(a[0]), "r"(a[1]), "r"(a[2]), "r"(a[3]), "r"(b0), "r"(b1));
}

__global__ __launch_bounds__(THREADS_, 2) void attn_kernel(
    const float* __restrict__ q, const float* __restrict__ k,
    const float* __restrict__ v, float* __restrict__ out) {
    extern __shared__ half smem[];
    half* sQh = smem;                  // [QT_][PADH] fp16 hi
    half* sKh = sQh + QT_ * PADH;
    half* sKl = sKh + KT_ * PADH;      // fp16 lo residual of K
    half* sVh = sKl + KT_ * PADH;      // [KT_][PADV]

    int bid = blockIdx.x;
    int qt = bid & 15;
    int h  = (bid >> 4) & 15;
    int n  = (bid >> 8) & 3;
    int b  = bid >> 10;

    int tid  = threadIdx.x;
    int warp = tid >> 5;
    int lane = tid & 31;
    int q0 = qt * QT_;

    // ---- load Q tile: RoPE -> fp16 ----
    {
        int p  = tid & 63;
        int r0 = tid >> 6;
        for (int r = r0; r < QT_; r += 2) {
            int gl = n * CHUNK_ + q0 + r;
            const float* row = q + ((size_t)((b * L_ + gl) * H_ + h)) * DH_;
            float x1 = row[p], x2 = row[p + 64];
            float2 cs = g_rope[gl * 64 + p];
            float y1 = x1 * cs.x - x2 * cs.y;
            float y2 = x2 * cs.x + x1 * cs.y;
            sQh[r * PADH + p]      = __float2half_rn(y1);
            sQh[r * PADH + p + 64] = __float2half_rn(y2);
        }
    }

    float acc[16][4];
#pragma unroll
    for (int i = 0; i < 16; i++)
#pragma unroll
        for (int j2 = 0; j2 < 4; j2++) acc[i][j2] = 0.f;
    float m0 = -1e30f, m1 = -1e30f, l0 = 0.f, l1 = 0.f;

    for (int kt = 0; kt <= qt; kt++) {
        __syncthreads();
        // ---- load K tile: RoPE + hi/lo split ----
        {
            int p  = tid & 63;
            int r0 = tid >> 6;
            for (int r = r0; r < KT_; r += 2) {
                int gl = n * CHUNK_ + kt * KT_ + r;
                const float* row = k + ((size_t)((b * L_ + gl) * H_ + h)) * DH_;
                float x1 = row[p], x2 = row[p + 64];
                float2 cs = g_rope[gl * 64 + p];
                float y1 = x1 * cs.x - x2 * cs.y;
                float y2 = x2 * cs.x + x1 * cs.y;
                half h1 = __float2half_rn(y1);
                half h2 = __float2half_rn(y2);
                sKh[r * PADH + p]      = h1;
                sKh[r * PADH + p + 64] = h2;
                sKl[r * PADH + p]      = __float2half_rn(y1 - __half2float(h1));
                sKl[r * PADH + p + 64] = __float2half_rn(y2 - __half2float(h2));
            }
        }
        // ---- load V tile (fp16) ----
        {
            int c4 = tid & 31;
            int r0 = tid >> 5;
            for (int r = r0; r < KT_; r += 4) {
                int gl = n * CHUNK_ + kt * KT_ + r;
                const float4* row =
                    (const float4*)(v + ((size_t)((b * L_ + gl) * H_ + h)) * DV_);
                float4 f = row[c4];
                half2 a01 = __floats2half2_rn(f.x, f.y);
                half2 a23 = __floats2half2_rn(f.z, f.w);
                *(half2*)&sVh[r * PADV + c4 * 4]     = a01;
                *(half2*)&sVh[r * PADV + c4 * 4 + 2] = a23;
            }
        }
        __syncthreads();

        // ---- S = Q K^T (Qh*Kh + Qh*Kl) ----
        float sacc[8][4];
#pragma unroll
        for (int j = 0; j < 8; j++)
#pragma unroll
            for (int j2 = 0; j2 < 4; j2++) sacc[j][j2] = 0.f;

#pragma unroll
        for (int ks = 0; ks < 8; ks++) {
            uint32_t aH[4];
            int aoff = (warp * 16 + (lane & 15)) * PADH + ks * 16 + ((lane >> 4) << 3);
            ldm_x4(aH, sQh + aoff);
#pragma unroll
            for (int jp = 0; jp < 4; jp++) {
                int g = lane >> 3;
                int boff = (jp * 16 + ((g >> 1) << 3) + (lane & 7)) * PADH +
                           ks * 16 + ((g & 1) << 3);
                uint32_t bH[4], bL[4];
                ldm_x4(bH, sKh + boff);
                ldm_x4(bL, sKl + boff);
                mma16816(sacc[2 * jp],     aH, bH[0], bH[1]);
                mma16816(sacc[2 * jp + 1], aH, bH[2], bH[3]);
                mma16816(sacc[2 * jp],     aH, bL[0], bL[1]);
                mma16816(sacc[2 * jp + 1], aH, bL[2], bL[3]);
            }
        }

        // ---- causal mask on diagonal tile ----
        if (kt == qt) {
            int r_lo = q0 + warp * 16 + (lane >> 2);
#pragma unroll
            for (int j = 0; j < 8; j++) {
                int c = qt * KT_ + j * 8 + ((lane & 3) << 1);
                if (c     > r_lo)     sacc[j][0] = -1e30f;
                if (c + 1 > r_lo)     sacc[j][1] = -1e30f;
                if (c     > r_lo + 8) sacc[j][2] = -1e30f;
                if (c + 1 > r_lo + 8) sacc[j][3] = -1e30f;
            }
        }

        // ---- online softmax (scale folded into exp) ----
        float mx0 = -1e30f, mx1 = -1e30f;
#pragma unroll
        for (int j = 0; j < 8; j++) {
            mx0 = fmaxf(mx0, fmaxf(sacc[j][0], sacc[j][1]));
            mx1 = fmaxf(mx1, fmaxf(sacc[j][2], sacc[j][3]));
        }
        mx0 = fmaxf(mx0, __shfl_xor_sync(0xffffffffu, mx0, 1));
        mx0 = fmaxf(mx0, __shfl_xor_sync(0xffffffffu, mx0, 2));
        mx1 = fmaxf(mx1, __shfl_xor_sync(0xffffffffu, mx1, 1));
        mx1 = fmaxf(mx1, __shfl_xor_sync(0xffffffffu, mx1, 2));
        float mn0 = fmaxf(m0, mx0), mn1 = fmaxf(m1, mx1);
        float al0 = __expf((m0 - mn0) * SCALE_);
        float al1 = __expf((m1 - mn1) * SCALE_);

        float rs0 = 0.f, rs1 = 0.f;
        uint32_t pH[8][2];
#pragma unroll
        for (int j = 0; j < 8; j++) {
            float p0 = __expf((sacc[j][0] - mn0) * SCALE_);
            float p1 = __expf((sacc[j][1] - mn0) * SCALE_);
            float p2 = __expf((sacc[j][2] - mn1) * SCALE_);
            float p3 = __expf((sacc[j][3] - mn1) * SCALE_);
            rs0 += p0 + p1;
            rs1 += p2 + p3;
            half2 t0 = __floats2half2_rn(p0, p1);
            half2 t1 = __floats2half2_rn(p2, p3);
            pH[j][0] = *(uint32_t*)&t0;
            pH[j][1] = *(uint32_t*)&t1;
        }
        rs0 += __shfl_xor_sync(0xffffffffu, rs0, 1);
        rs0 += __shfl_xor_sync(0xffffffffu, rs0, 2);
        rs1 += __shfl_xor_sync(0xffffffffu, rs1, 1);
        rs1 += __shfl_xor_sync(0xffffffffu, rs1, 2);
        l0 = l0 * al0 + rs0;
        l1 = l1 * al1 + rs1;
        m0 = mn0;
        m1 = mn1;
#pragma unroll
        for (int nt = 0; nt < 16; nt++) {
            acc[nt][0] *= al0;
            acc[nt][1] *= al0;
            acc[nt][2] *= al1;
            acc[nt][3] *= al1;
        }

        // ---- O += P V ----
#pragma unroll
        for (int kk = 0; kk < 4; kk++) {
            uint32_t a[4] = {pH[2 * kk][0], pH[2 * kk][1],
                             pH[2 * kk + 1][0], pH[2 * kk + 1][1]};
#pragma unroll
            for (int nb = 0; nb < 8; nb++) {
                int g = lane >> 3;
                int voff = (kk * 16 + ((g & 1) << 3) + (lane & 7)) * PADV +
                           nb * 16 + ((g >> 1) << 3);
                uint32_t bv[4];
                ldm_x4_t(bv, sVh + voff);
                mma16816(acc[2 * nb],     a, bv[0], bv[1]);
                mma16816(acc[2 * nb + 1], a, bv[2], bv[3]);
            }
        }
    }

    // ---- normalize and write out ----
    float il0 = 1.f / l0, il1 = 1.f / l1;
    int gl0 = n * CHUNK_ + q0 + warp * 16 + (lane >> 2);
    float* o0 = out + ((size_t)((b * L_ + gl0) * H_ + h)) * DV_;
    float* o1 = out + ((size_t)((b * L_ + gl0 + 8) * H_ + h)) * DV_;
#pragma unroll
    for (int nt = 0; nt < 16; nt++) {
        int c = nt * 8 + ((lane & 3) << 1);
        float2 w0 = make_float2(acc[nt][0] * il0, acc[nt][1] * il0);
        float2 w1 = make_float2(acc[nt][2] * il1, acc[nt][3] * il1);
        *(float2*)(o0 + c) = w0;
        *(float2*)(o1 + c) = w1;
    }
}

extern "C" void kernel_launch(void* const* d_in, const int* in_sizes, int n_in,
                              void* d_out, int out_size) {
    (void)in_sizes; (void)n_in; (void)out_size;
    const float* q = (const float*)d_in[0];
    const float* k = (const float*)d_in[1];
    const float* v = (const float*)d_in[2];
    float* out = (float*)d_out;

    cudaFuncSetAttribute(attn_kernel, cudaFuncAttributeMaxDynamicSharedMemorySize,
                         SMEM_BYTES);
    rope_table_kernel<<<(L_ * 64 + 255) / 256, 256>>>();
    attn_kernel<<<B_ * NCHUNK_ * H_ * 16, THREADS_, SMEM_BYTES>>>(q, k, v, out);
}

// round 6
// speedup vs baseline: 3.0537x; 2.7015x over previous
#include <cuda_runtime.h>
#include <cuda_fp16.h>
#include <cstdint>
#include <math.h>

#define B_ 4
#define L_ 4096
#define H_ 16
#define DH_ 128
#define DV_ 128
#define CHUNK_ 1024
#define NCHUNK_ 4
#define QT_ 64
#define KT_ 64
#define THREADS_ 128
#define SCALE_ 0.08838834764831845f  /* 1/sqrt(128) */

#define TILE_HALVES (64 * 128)          /* one 64x128 fp16 tile */
#define TILE_BYTES_ (TILE_HALVES * 2)   /* 16384 */
#define SMEM_BYTES (7 * TILE_BYTES_)    /* Q + 2 stages x (Kh,Kl,Vh) = 112KB */

// RoPE cos/sin table: [L_][64] of (cos, sin)
__device__ float2 g_rope[L_ * 64];

// Pre-transformed fp16 tensors, layout [b, l, h, d]
__device__ __half g_qh[B_ * L_ * H_ * DH_];
__device__ __half g_kh[B_ * L_ * H_ * DH_];
__device__ __half g_kl[B_ * L_ * H_ * DH_];
__device__ __half g_vh[B_ * L_ * H_ * DV_];

__global__ void rope_table_kernel() {
    int idx = blockIdx.x * blockDim.x + threadIdx.x;
    if (idx >= L_ * 64) return;
    int pos = idx >> 6;
    int j = idx & 63;
    const float coef = -0.14391156831212787f;  // -ln(10000)/64
    float freq = expf((float)j * coef);
    float ang = (float)pos * freq;   // fp32 rounding matches reference
    float s, c;
    sincosf(ang, &s, &c);
    g_rope[idx] = make_float2(c, s);
}

// RoPE + fp16 conversion pre-pass: one thread handles dim pair (p, p+64) of one row
__global__ void prepass_kernel(const float* __restrict__ q,
                               const float* __restrict__ k,
                               const float* __restrict__ v) {
    int idx = blockIdx.x * blockDim.x + threadIdx.x;
    if (idx >= B_ * L_ * H_ * 64) return;
    int p  = idx & 63;
    int rh = idx >> 6;                 // (b*L + l)*H + h
    int gl = (rh >> 4) & (L_ - 1);     // l  (H_=16)
    size_t base = (size_t)rh * 128;
    float2 cs = g_rope[gl * 64 + p];

    float x1 = q[base + p], x2 = q[base + p + 64];
    g_qh[base + p]      = __float2half_rn(x1 * cs.x - x2 * cs.y);
    g_qh[base + p + 64] = __float2half_rn(x2 * cs.x + x1 * cs.y);

    x1 = k[base + p]; x2 = k[base + p + 64];
    float y1 = x1 * cs.x - x2 * cs.y;
    float y2 = x2 * cs.x + x1 * cs.y;
    __half h1 = __float2half_rn(y1);
    __half h2 = __float2half_rn(y2);
    g_kh[base + p]      = h1;
    g_kh[base + p + 64] = h2;
    g_kl[base + p]      = __float2half_rn(y1 - __half2float(h1));
    g_kl[base + p + 64] = __float2half_rn(y2 - __half2float(h2));

    g_vh[base + p]      = __float2half_rn(v[base + p]);
    g_vh[base + p + 64] = __float2half_rn(v[base + p + 64]);
}

__device__ __forceinline__ void ldm_x4(uint32_t r[4], uint32_t a) {
    asm volatile("ldmatrix.sync.aligned.m8n8.x4.shared.b16 {%0,%1,%2,%3}, [%4];\n"
                 : "=r"(r[0]), "=r"(r[1]), "=r"(r[2]), "=r"(r[3]) : "r"(a));
}
__device__ __forceinline__ void ldm_x4_t(uint32_t r[4], uint32_t a) {
    asm volatile("ldmatrix.sync.aligned.m8n8.x4.trans.shared.b16 {%0,%1,%2,%3}, [%4];\n"
                 : "=r"(r[0]), "=r"(r[1]), "=r"(r[2]), "=r"(r[3]) : "r"(a));
}
__device__ __forceinline__ void mma16816(float c[4], const uint32_t a[4],
                                         uint32_t b0, uint32_t b1) {
    asm volatile(
        "mma.sync.aligned.m16n8k16.row.col.f32.f16.f16.f32 "
        "{%0,%1,%2,%3}, {%4,%5,%6,%7}, {%8,%9}, {%0,%1,%2,%3};\n"
        : "+f"(c[0]), "+f"(c[1]), "+f"(c[2]), "+f"(c[3])
        : "r"(a[0]), "r"(a[1]), "r"(a[2]), "r"(a[3]), "r"(b0), "r"(b1));
}
__device__ __forceinline__ void cp16(uint32_t dst, const void* src) {
    asm volatile("cp.async.cg.shared.global [%0], [%1], 16;\n" :: "r"(dst), "l"(src));
}

// swizzled byte offset inside a 64x128-half tile: row-major 256B rows,
// 16B chunk index XORed with (row & 7)
__device__ __forceinline__ uint32_t sw_off(int row, int chunk) {
    return (uint32_t)((row << 8) + ((chunk ^ (row & 7)) << 4));
}

// copy one 64x128 fp16 tile gmem -> smem (swizzled), 128 threads
__device__ __forceinline__ void copy_tile(uint32_t dst, const __half* src, int tid) {
#pragma unroll
    for (int i = 0; i < 8; i++) {
        int t = tid + i * 128;       // 0..1023
        int row = t >> 4, ch = t & 15;
        cp16(dst + sw_off(row, ch), src + (size_t)row * 2048 + ch * 8);
    }
}

__global__ __launch_bounds__(THREADS_, 2) void attn_kernel(float* __restrict__ out) {
    extern __shared__ __half smem[];
    uint32_t sbase = (uint32_t)__cvta_generic_to_shared(smem);
    uint32_t sQ = sbase;
    // stage s: Kh, Kl, Vh
    uint32_t sKh[2] = {sbase + TILE_BYTES_,     sbase + 4 * TILE_BYTES_};
    uint32_t sKl[2] = {sbase + 2 * TILE_BYTES_, sbase + 5 * TILE_BYTES_};
    uint32_t sVh[2] = {sbase + 3 * TILE_BYTES_, sbase + 6 * TILE_BYTES_};

    int bid = blockIdx.x;
    int qt = bid & 15;
    int h  = (bid >> 4) & 15;
    int n  = (bid >> 8) & 3;
    int b  = bid >> 10;

    int tid  = threadIdx.x;
    int warp = tid >> 5;
    int lane = tid & 31;
    int q0 = qt * QT_;

    const size_t head_off = ((size_t)(b * L_ + n * CHUNK_) * H_ + h) * 128;
    const __half* qsrc = g_qh + head_off + (size_t)q0 * 2048;
    const __half* khsrc = g_kh + head_off;
    const __half* klsrc = g_kl + head_off;
    const __half* vhsrc = g_vh + head_off;

    // prefetch Q tile + kt=0 tiles as group 0
    copy_tile(sQ, qsrc, tid);
    copy_tile(sKh[0], khsrc, tid);
    copy_tile(sKl[0], klsrc, tid);
    copy_tile(sVh[0], vhsrc, tid);
    asm volatile("cp.async.commit_group;\n");

    float acc[16][4];
#pragma unroll
    for (int i = 0; i < 16; i++)
#pragma unroll
        for (int j2 = 0; j2 < 4; j2++) acc[i][j2] = 0.f;
    float m0 = -1e30f, m1 = -1e30f, l0 = 0.f, l1 = 0.f;

    // precomputed fragment coordinates
    int g = lane >> 3;
    int arow = warp * 16 + (lane & 15);
    int achk = lane >> 4;                       // + ks*2
    int brow_b = ((g >> 1) << 3) + (lane & 7);  // + jp*16
    int bchk = g & 1;                           // + ks*2
    int vrow_b = ((g & 1) << 3) + (lane & 7);   // + kk*16
    int vchk = g >> 1;                          // + nb*2

    for (int kt = 0; kt <= qt; kt++) {
        int cur = kt & 1;
        if (kt < qt) {
            int nxt = cur ^ 1;
            size_t toff = (size_t)(kt + 1) * KT_ * 2048;
            copy_tile(sKh[nxt], khsrc + toff, tid);
            copy_tile(sKl[nxt], klsrc + toff, tid);
            copy_tile(sVh[nxt], vhsrc + toff, tid);
            asm volatile("cp.async.commit_group;\n");
            asm volatile("cp.async.wait_group 1;\n");
        } else {
            asm volatile("cp.async.wait_group 0;\n");
        }
        __syncthreads();

        // ---- S = Q K^T (Qh*Kh + Qh*Kl) ----
        float sacc[8][4];
#pragma unroll
        for (int j = 0; j < 8; j++)
#pragma unroll
            for (int j2 = 0; j2 < 4; j2++) sacc[j][j2] = 0.f;

#pragma unroll
        for (int ks = 0; ks < 8; ks++) {
            uint32_t aH[4];
            ldm_x4(aH, sQ + sw_off(arow, ks * 2 + achk));
#pragma unroll
            for (int jp = 0; jp < 4; jp++) {
                int brow = jp * 16 + brow_b;
                uint32_t bo = sw_off(brow, ks * 2 + bchk);
                uint32_t bH[4], bL[4];
                ldm_x4(bH, sKh[cur] + bo);
                ldm_x4(bL, sKl[cur] + bo);
                mma16816(sacc[2 * jp],     aH, bH[0], bH[1]);
                mma16816(sacc[2 * jp + 1], aH, bH[2], bH[3]);
                mma16816(sacc[2 * jp],     aH, bL[0], bL[1]);
                mma16816(sacc[2 * jp + 1], aH, bL[2], bL[3]);
            }
        }

        // ---- causal mask on diagonal tile ----
        if (kt == qt) {
            int r_lo = q0 + warp * 16 + (lane >> 2);
#pragma unroll
            for (int j = 0; j < 8; j++) {
                int c = qt * KT_ + j * 8 + ((lane & 3) << 1);
                if (c     > r_lo)     sacc[j][0] = -1e30f;
                if (c + 1 > r_lo)     sacc[j][1] = -1e30f;
                if (c     > r_lo + 8) sacc[j][2] = -1e30f;
                if (c + 1 > r_lo + 8) sacc[j][3] = -1e30f;
            }
        }

        // ---- online softmax ----
        float mx0 = -1e30f, mx1 = -1e30f;
#pragma unroll
        for (int j = 0; j < 8; j++) {
            mx0 = fmaxf(mx0, fmaxf(sacc[j][0], sacc[j][1]));
            mx1 = fmaxf(mx1, fmaxf(sacc[j][2], sacc[j][3]));
        }
        mx0 = fmaxf(mx0, __shfl_xor_sync(0xffffffffu, mx0, 1));
        mx0 = fmaxf(mx0, __shfl_xor_sync(0xffffffffu, mx0, 2));
        mx1 = fmaxf(mx1, __shfl_xor_sync(0xffffffffu, mx1, 1));
        mx1 = fmaxf(mx1, __shfl_xor_sync(0xffffffffu, mx1, 2));
        float mn0 = fmaxf(m0, mx0), mn1 = fmaxf(m1, mx1);
        float al0 = __expf((m0 - mn0) * SCALE_);
        float al1 = __expf((m1 - mn1) * SCALE_);

        float rs0 = 0.f, rs1 = 0.f;
        uint32_t pH[8][2];
#pragma unroll
        for (int j = 0; j < 8; j++) {
            float p0 = __expf((sacc[j][0] - mn0) * SCALE_);
            float p1 = __expf((sacc[j][1] - mn0) * SCALE_);
            float p2 = __expf((sacc[j][2] - mn1) * SCALE_);
            float p3 = __expf((sacc[j][3] - mn1) * SCALE_);
            rs0 += p0 + p1;
            rs1 += p2 + p3;
            half2 t0 = __floats2half2_rn(p0, p1);
            half2 t1 = __floats2half2_rn(p2, p3);
            pH[j][0] = *(uint32_t*)&t0;
            pH[j][1] = *(uint32_t*)&t1;
        }
        rs0 += __shfl_xor_sync(0xffffffffu, rs0, 1);
        rs0 += __shfl_xor_sync(0xffffffffu, rs0, 2);
        rs1 += __shfl_xor_sync(0xffffffffu, rs1, 1);
        rs1 += __shfl_xor_sync(0xffffffffu, rs1, 2);
        l0 = l0 * al0 + rs0;
        l1 = l1 * al1 + rs1;
        m0 = mn0;
        m1 = mn1;
#pragma unroll
        for (int nt = 0; nt < 16; nt++) {
            acc[nt][0] *= al0;
            acc[nt][1] *= al0;
            acc[nt][2] *= al1;
            acc[nt][3] *= al1;
        }

        // ---- O += P V ----
#pragma unroll
        for (int kk = 0; kk < 4; kk++) {
            uint32_t a[4] = {pH[2 * kk][0], pH[2 * kk][1],
                             pH[2 * kk + 1][0], pH[2 * kk + 1][1]};
            int vrow = kk * 16 + vrow_b;
#pragma unroll
            for (int nb = 0; nb < 8; nb++) {
                uint32_t bv[4];
                ldm_x4_t(bv, sVh[cur] + sw_off(vrow, nb * 2 + vchk));
                mma16816(acc[2 * nb],     a, bv[0], bv[1]);
                mma16816(acc[2 * nb + 1], a, bv[2], bv[3]);
            }
        }
        __syncthreads();
    }

    // ---- normalize and write out ----
    float il0 = 1.f / l0, il1 = 1.f / l1;
    int gl0 = n * CHUNK_ + q0 + warp * 16 + (lane >> 2);
    float* o0 = out + ((size_t)((b * L_ + gl0) * H_ + h)) * DV_;
    float* o1 = out + ((size_t)((b * L_ + gl0 + 8) * H_ + h)) * DV_;
#pragma unroll
    for (int nt = 0; nt < 16; nt++) {
        int c = nt * 8 + ((lane & 3) << 1);
        float2 w0 = make_float2(acc[nt][0] * il0, acc[nt][1] * il0);
        float2 w1 = make_float2(acc[nt][2] * il1, acc[nt][3] * il1);
        *(float2*)(o0 + c) = w0;
        *(float2*)(o1 + c) = w1;
    }
}

extern "C" void kernel_launch(void* const* d_in, const int* in_sizes, int n_in,
                              void* d_out, int out_size) {
    (void)in_sizes; (void)n_in; (void)out_size;
    const float* q = (const float*)d_in[0];
    const float* k = (const float*)d_in[1];
    const float* v = (const float*)d_in[2];
    float* out = (float*)d_out;

    cudaFuncSetAttribute(attn_kernel, cudaFuncAttributeMaxDynamicSharedMemorySize,
                         SMEM_BYTES);
    rope_table_kernel<<<(L_ * 64 + 255) / 256, 256>>>();
    prepass_kernel<<<(B_ * L_ * H_ * 64 + 255) / 256, 256>>>(q, k, v);
    attn_kernel<<<B_ * NCHUNK_ * H_ * 16, THREADS_, SMEM_BYTES>>>(out);
}

// round 7
// speedup vs baseline: 3.8047x; 1.2459x over previous
#include <cuda_runtime.h>
#include <cuda_fp16.h>
#include <cstdint>
#include <math.h>

#define B_ 4
#define L_ 4096
#define H_ 16
#define DH_ 128
#define DV_ 128
#define CHUNK_ 1024
#define NCHUNK_ 4
#define QT_ 64
#define KT_ 64
#define THREADS_ 128
#define SCALE_ 0.08838834764831845f  /* 1/sqrt(128) */

#define TILE_HALVES (64 * 128)          /* one 64x128 fp16 tile */
#define TILE_BYTES_ (TILE_HALVES * 2)   /* 16384 */
#define SMEM_BYTES (7 * TILE_BYTES_)    /* Q + 3 stages x (Kh,Vh) = 112KB */

// RoPE cos/sin table: [L_][64] of (cos, sin)
__device__ float2 g_rope[L_ * 64];

// Pre-transformed fp16 tensors, layout [b, l, h, d]
__device__ __half g_qh[B_ * L_ * H_ * DH_];
__device__ __half g_kh[B_ * L_ * H_ * DH_];
__device__ __half g_vh[B_ * L_ * H_ * DV_];

__global__ void rope_table_kernel() {
    int idx = blockIdx.x * blockDim.x + threadIdx.x;
    if (idx >= L_ * 64) return;
    int pos = idx >> 6;
    int j = idx & 63;
    const float coef = -0.14391156831212787f;  // -ln(10000)/64
    float freq = expf((float)j * coef);
    float ang = (float)pos * freq;   // fp32 rounding matches reference
    float s, c;
    sincosf(ang, &s, &c);
    g_rope[idx] = make_float2(c, s);
}

// RoPE + fp16 conversion pre-pass: one thread handles dim pair (p, p+64) of one row
__global__ void prepass_kernel(const float* __restrict__ q,
                               const float* __restrict__ k,
                               const float* __restrict__ v) {
    int idx = blockIdx.x * blockDim.x + threadIdx.x;
    if (idx >= B_ * L_ * H_ * 64) return;
    int p  = idx & 63;
    int rh = idx >> 6;                 // (b*L + l)*H + h
    int gl = (rh >> 4) & (L_ - 1);     // l  (H_=16)
    size_t base = (size_t)rh * 128;
    float2 cs = g_rope[gl * 64 + p];

    float x1 = q[base + p], x2 = q[base + p + 64];
    g_qh[base + p]      = __float2half_rn(x1 * cs.x - x2 * cs.y);
    g_qh[base + p + 64] = __float2half_rn(x2 * cs.x + x1 * cs.y);

    x1 = k[base + p]; x2 = k[base + p + 64];
    g_kh[base + p]      = __float2half_rn(x1 * cs.x - x2 * cs.y);
    g_kh[base + p + 64] = __float2half_rn(x2 * cs.x + x1 * cs.y);

    g_vh[base + p]      = __float2half_rn(v[base + p]);
    g_vh[base + p + 64] = __float2half_rn(v[base + p + 64]);
}

__device__ __forceinline__ void ldm_x4(uint32_t r[4], uint32_t a) {
    asm volatile("ldmatrix.sync.aligned.m8n8.x4.shared.b16 {%0,%1,%2,%3}, [%4];\n"
                 : "=r"(r[0]), "=r"(r[1]), "=r"(r[2]), "=r"(r[3]) : "r"(a));
}
__device__ __forceinline__ void ldm_x4_t(uint32_t r[4], uint32_t a) {
    asm volatile("ldmatrix.sync.aligned.m8n8.x4.trans.shared.b16 {%0,%1,%2,%3}, [%4];\n"
                 : "=r"(r[0]), "=r"(r[1]), "=r"(r[2]), "=r"(r[3]) : "r"(a));
}
__device__ __forceinline__ void mma16816(float c[4], const uint32_t a[4],
                                         uint32_t b0, uint32_t b1) {
    asm volatile(
        "mma.sync.aligned.m16n8k16.row.col.f32.f16.f16.f32 "
        "{%0,%1,%2,%3}, {%4,%5,%6,%7}, {%8,%9}, {%0,%1,%2,%3};\n"
        : "+f"(c[0]), "+f"(c[1]), "+f"(c[2]), "+f"(c[3])
        : "r"(a[0]), "r"(a[1]), "r"(a[2]), "r"(a[3]), "r"(b0), "r"(b1));
}
__device__ __forceinline__ void cp16(uint32_t dst, const void* src) {
    asm volatile("cp.async.cg.shared.global [%0], [%1], 16;\n" :: "r"(dst), "l"(src));
}

// swizzled byte offset inside a 64x128-half tile: row-major 256B rows,
// 16B chunk index XORed with (row & 7)
__device__ __forceinline__ uint32_t sw_off(int row, int chunk) {
    return (uint32_t)((row << 8) + ((chunk ^ (row & 7)) << 4));
}

// copy one 64x128 fp16 tile gmem -> smem (swizzled), 128 threads
__device__ __forceinline__ void copy_tile(uint32_t dst, const __half* src, int tid) {
#pragma unroll
    for (int i = 0; i < 8; i++) {
        int t = tid + i * 128;       // 0..1023
        int row = t >> 4, ch = t & 15;
        cp16(dst + sw_off(row, ch), src + (size_t)row * 2048 + ch * 8);
    }
}

__global__ __launch_bounds__(THREADS_, 2) void attn_kernel(float* __restrict__ out) {
    extern __shared__ __half smem[];
    uint32_t sbase = (uint32_t)__cvta_generic_to_shared(smem);
    uint32_t sQ = sbase;
    uint32_t sKh[3] = {sbase + 1 * TILE_BYTES_, sbase + 3 * TILE_BYTES_,
                       sbase + 5 * TILE_BYTES_};
    uint32_t sVh[3] = {sbase + 2 * TILE_BYTES_, sbase + 4 * TILE_BYTES_,
                       sbase + 6 * TILE_BYTES_};

    int bid = blockIdx.x;
    int qt = bid & 15;
    int h  = (bid >> 4) & 15;
    int n  = (bid >> 8) & 3;
    int b  = bid >> 10;

    int tid  = threadIdx.x;
    int warp = tid >> 5;
    int lane = tid & 31;
    int q0 = qt * QT_;

    const size_t head_off = ((size_t)(b * L_ + n * CHUNK_) * H_ + h) * 128;
    const __half* qsrc  = g_qh + head_off + (size_t)q0 * 2048;
    const __half* khsrc = g_kh + head_off;
    const __half* vhsrc = g_vh + head_off;

    // prologue: Q + tile0 as group; tile1 as second group
    copy_tile(sQ, qsrc, tid);
    copy_tile(sKh[0], khsrc, tid);
    copy_tile(sVh[0], vhsrc, tid);
    asm volatile("cp.async.commit_group;\n");
    if (qt >= 1) {
        copy_tile(sKh[1], khsrc + (size_t)KT_ * 2048, tid);
        copy_tile(sVh[1], vhsrc + (size_t)KT_ * 2048, tid);
        asm volatile("cp.async.commit_group;\n");
    }

    float acc[16][4];
#pragma unroll
    for (int i = 0; i < 16; i++)
#pragma unroll
        for (int j2 = 0; j2 < 4; j2++) acc[i][j2] = 0.f;
    float m0 = -1e30f, m1 = -1e30f, l0 = 0.f, l1 = 0.f;

    // precomputed fragment coordinates
    int g = lane >> 3;
    int arow = warp * 16 + (lane & 15);
    int achk = lane >> 4;                       // + ks*2
    int brow_b = ((g >> 1) << 3) + (lane & 7);  // + jp*16
    int bchk = g & 1;                           // + ks*2
    int vrow_b = ((g & 1) << 3) + (lane & 7);   // + kk*16
    int vchk = g >> 1;                          // + nb*2

    for (int kt = 0; kt <= qt; kt++) {
        int cur = kt % 3;
        if (kt < qt) {
            asm volatile("cp.async.wait_group 1;\n");
        } else {
            asm volatile("cp.async.wait_group 0;\n");
        }
        __syncthreads();

        // prefetch kt+2 (stage was fully consumed at iter kt-1)
        if (kt + 2 <= qt) {
            int st = (kt + 2) % 3;
            size_t toff = (size_t)(kt + 2) * KT_ * 2048;
            copy_tile(sKh[st], khsrc + toff, tid);
            copy_tile(sVh[st], vhsrc + toff, tid);
            asm volatile("cp.async.commit_group;\n");
        }

        // ---- S = Q K^T ----
        float sacc[8][4];
#pragma unroll
        for (int j = 0; j < 8; j++)
#pragma unroll
            for (int j2 = 0; j2 < 4; j2++) sacc[j][j2] = 0.f;

#pragma unroll
        for (int ks = 0; ks < 8; ks++) {
            uint32_t aH[4];
            ldm_x4(aH, sQ + sw_off(arow, ks * 2 + achk));
#pragma unroll
            for (int jp = 0; jp < 4; jp++) {
                int brow = jp * 16 + brow_b;
                uint32_t bH[4];
                ldm_x4(bH, sKh[cur] + sw_off(brow, ks * 2 + bchk));
                mma16816(sacc[2 * jp],     aH, bH[0], bH[1]);
                mma16816(sacc[2 * jp + 1], aH, bH[2], bH[3]);
            }
        }

        // ---- causal mask on diagonal tile ----
        if (kt == qt) {
            int r_lo = q0 + warp * 16 + (lane >> 2);
#pragma unroll
            for (int j = 0; j < 8; j++) {
                int c = qt * KT_ + j * 8 + ((lane & 3) << 1);
                if (c     > r_lo)     sacc[j][0] = -1e30f;
                if (c + 1 > r_lo)     sacc[j][1] = -1e30f;
                if (c     > r_lo + 8) sacc[j][2] = -1e30f;
                if (c + 1 > r_lo + 8) sacc[j][3] = -1e30f;
            }
        }

        // ---- online softmax ----
        float mx0 = -1e30f, mx1 = -1e30f;
#pragma unroll
        for (int j = 0; j < 8; j++) {
            mx0 = fmaxf(mx0, fmaxf(sacc[j][0], sacc[j][1]));
            mx1 = fmaxf(mx1, fmaxf(sacc[j][2], sacc[j][3]));
        }
        mx0 = fmaxf(mx0, __shfl_xor_sync(0xffffffffu, mx0, 1));
        mx0 = fmaxf(mx0, __shfl_xor_sync(0xffffffffu, mx0, 2));
        mx1 = fmaxf(mx1, __shfl_xor_sync(0xffffffffu, mx1, 1));
        mx1 = fmaxf(mx1, __shfl_xor_sync(0xffffffffu, mx1, 2));
        float mn0 = fmaxf(m0, mx0), mn1 = fmaxf(m1, mx1);
        float al0 = __expf((m0 - mn0) * SCALE_);
        float al1 = __expf((m1 - mn1) * SCALE_);

        float rs0 = 0.f, rs1 = 0.f;
        uint32_t pH[8][2];
#pragma unroll
        for (int j = 0; j < 8; j++) {
            float p0 = __expf((sacc[j][0] - mn0) * SCALE_);
            float p1 = __expf((sacc[j][1] - mn0) * SCALE_);
            float p2 = __expf((sacc[j][2] - mn1) * SCALE_);
            float p3 = __expf((sacc[j][3] - mn1) * SCALE_);
            rs0 += p0 + p1;
            rs1 += p2 + p3;
            half2 t0 = __floats2half2_rn(p0, p1);
            half2 t1 = __floats2half2_rn(p2, p3);
            pH[j][0] = *(uint32_t*)&t0;
            pH[j][1] = *(uint32_t*)&t1;
        }
        rs0 += __shfl_xor_sync(0xffffffffu, rs0, 1);
        rs0 += __shfl_xor_sync(0xffffffffu, rs0, 2);
        rs1 += __shfl_xor_sync(0xffffffffu, rs1, 1);
        rs1 += __shfl_xor_sync(0xffffffffu, rs1, 2);
        l0 = l0 * al0 + rs0;
        l1 = l1 * al1 + rs1;
        m0 = mn0;
        m1 = mn1;
#pragma unroll
        for (int nt = 0; nt < 16; nt++) {
            acc[nt][0] *= al0;
            acc[nt][1] *= al0;
            acc[nt][2] *= al1;
            acc[nt][3] *= al1;
        }

        // ---- O += P V ----
#pragma unroll
        for (int kk = 0; kk < 4; kk++) {
            uint32_t a[4] = {pH[2 * kk][0], pH[2 * kk][1],
                             pH[2 * kk + 1][0], pH[2 * kk + 1][1]};
            int vrow = kk * 16 + vrow_b;
#pragma unroll
            for (int nb = 0; nb < 8; nb++) {
                uint32_t bv[4];
                ldm_x4_t(bv, sVh[cur] + sw_off(vrow, nb * 2 + vchk));
                mma16816(acc[2 * nb],     a, bv[0], bv[1]);
                mma16816(acc[2 * nb + 1], a, bv[2], bv[3]);
            }
        }
    }

    // ---- normalize and write out ----
    float il0 = 1.f / l0, il1 = 1.f / l1;
    int gl0 = n * CHUNK_ + q0 + warp * 16 + (lane >> 2);
    float* o0 = out + ((size_t)((b * L_ + gl0) * H_ + h)) * DV_;
    float* o1 = out + ((size_t)((b * L_ + gl0 + 8) * H_ + h)) * DV_;
#pragma unroll
    for (int nt = 0; nt < 16; nt++) {
        int c = nt * 8 + ((lane & 3) << 1);
        float2 w0 = make_float2(acc[nt][0] * il0, acc[nt][1] * il0);
        float2 w1 = make_float2(acc[nt][2] * il1, acc[nt][3] * il1);
        *(float2*)(o0 + c) = w0;
        *(float2*)(o1 + c) = w1;
    }
}

extern "C" void kernel_launch(void* const* d_in, const int* in_sizes, int n_in,
                              void* d_out, int out_size) {
    (void)in_sizes; (void)n_in; (void)out_size;
    const float* q = (const float*)d_in[0];
    const float* k = (const float*)d_in[1];
    const float* v = (const float*)d_in[2];
    float* out = (float*)d_out;

    cudaFuncSetAttribute(attn_kernel, cudaFuncAttributeMaxDynamicSharedMemorySize,
                         SMEM_BYTES);
    rope_table_kernel<<<(L_ * 64 + 255) / 256, 256>>>();
    prepass_kernel<<<(B_ * L_ * H_ * 64 + 255) / 256, 256>>>(q, k, v);
    attn_kernel<<<B_ * NCHUNK_ * H_ * 16, THREADS_, SMEM_BYTES>>>(out);
}